// round 16
// baseline (speedup 1.0000x reference)
#include <cuda_runtime.h>
#include <math.h>

#define TT 2048
#define HH 1024
#define II 1024
#define NE 16
#define KTOP 4
#define EPSF 1e-5f
#define ALPHAF 1.702f
#define LIMITF 7.0f

#define BM 128
#define BN 128
#define BK 32
#define PAD 36                                  // 32 + 4; 36 mod 32 = 4 -> conflict-free LDSM
#define NSTG 3
#define STG_WORDS (128 * PAD)                   // 4608 words = 18432 B
#define STGB (STG_WORDS * 4)
#define SMEM_BYTES (NSTG * STGB * 2)            // 110592 -> 2 CTAs/SM = 216 KB

#define TOK_PER_BLK 8
#define NG_SMEM ((NE * HH + HH) * 4)            // 69632

// ---------------- scratch (static device globals; no allocation) -------------
__device__ __align__(16) float g_t[TT * HH];            // tf32-rounded rmsnorm out
__device__ __align__(16) float g_s[TT * KTOP * II];     // tf32-rounded swiglu out
__device__ __align__(16) float g_y[TT * KTOP * HH];
__device__ __align__(16) float g_w1r[NE * II * HH];     // tf32-rounded, even w1 rows gathered
__device__ __align__(16) float g_w2r[NE * HH * II];     // tf32-rounded w2
__device__ float g_slot_w[TT * KTOP];
__device__ int   g_expert_cnt[NE];
__device__ int   g_expert_slots[NE * TT];

// ---------------- helpers ------------------------------------------------------
__device__ __forceinline__ unsigned f2tf(float f) {
    unsigned r;
    asm("cvt.rna.tf32.f32 %0, %1;" : "=r"(r) : "f"(f));
    return r;
}

__device__ __forceinline__ void mma_tf32(float* d, const unsigned* a, const unsigned* b) {
    asm volatile(
        "mma.sync.aligned.m16n8k8.row.col.f32.tf32.tf32.f32 "
        "{%0,%1,%2,%3}, {%4,%5,%6,%7}, {%8,%9}, {%0,%1,%2,%3};"
        : "+f"(d[0]), "+f"(d[1]), "+f"(d[2]), "+f"(d[3])
        : "r"(a[0]), "r"(a[1]), "r"(a[2]), "r"(a[3]), "r"(b[0]), "r"(b[1]));
}

__device__ __forceinline__ void ldsm4(unsigned* r, unsigned addr) {
    asm volatile("ldmatrix.sync.aligned.m8n8.x4.shared.b16 {%0,%1,%2,%3}, [%4];"
        : "=r"(r[0]), "=r"(r[1]), "=r"(r[2]), "=r"(r[3]) : "r"(addr));
}

__device__ __forceinline__ void cp16(unsigned dst, const void* src) {
    asm volatile("cp.async.cg.shared.global [%0], [%1], 16;" :: "r"(dst), "l"(src));
}
#define CP_COMMIT() asm volatile("cp.async.commit_group;")
#define CP_WAIT1()  asm volatile("cp.async.wait_group 1;")

// ---------------- kernel 0 -----------------------------------------------------
__global__ void zero_cnt_kernel() {
    if (threadIdx.x < NE) g_expert_cnt[threadIdx.x] = 0;
}

// ---------------- prep: round weights to tf32 scratch (w1: even rows gathered) -
__global__ void prep_w1_kernel(const float* __restrict__ w1) {
    int idx = blockIdx.x * 256 + threadIdx.x;     // float4 index
    int r = idx >> 8;                              // global row in [0, NE*II)
    int q = idx & 255;
    int e = r >> 10, n = r & 1023;
    float4 v = *((const float4*)(w1 + ((size_t)e * 2 * II + 2 * n) * HH) + q);
    uint4 u;
    u.x = f2tf(v.x); u.y = f2tf(v.y); u.z = f2tf(v.z); u.w = f2tf(v.w);
    *((uint4*)(g_w1r + (size_t)r * HH) + q) = u;
}

__global__ void prep_w2_kernel(const float* __restrict__ w2) {
    size_t idx = (size_t)blockIdx.x * 256 + threadIdx.x;  // float4 index
    float4 v = *((const float4*)w2 + idx);
    uint4 u;
    u.x = f2tf(v.x); u.y = f2tf(v.y); u.z = f2tf(v.z); u.w = f2tf(v.w);
    *((uint4*)g_w2r + idx) = u;
}

// ---------------- kernel 1: RMSNorm + gate + top4, 8 tokens/block -------------
__global__ void norm_gate_kernel(const float* __restrict__ x,
                                 const float* __restrict__ scale,
                                 const float* __restrict__ gate_w,
                                 const float* __restrict__ gate_b) {
    extern __shared__ float sm[];
    float* gw = sm;                 // [NE*HH]
    float* ts = sm + NE * HH;       // [HH]
    __shared__ float gv[NE];
    __shared__ float red[8];
    int tid = threadIdx.x;

    for (int i = tid; i < NE * HH / 4; i += 256)
        ((float4*)gw)[i] = ((const float4*)gate_w)[i];
    __syncthreads();

    float4 sc = *((const float4*)scale + tid);

    for (int tt = 0; tt < TOK_PER_BLK; tt++) {
        int t = blockIdx.x * TOK_PER_BLK + tt;
        float4 v = *((const float4*)(x + (size_t)t * HH) + tid);
        float ss = v.x * v.x + v.y * v.y + v.z * v.z + v.w * v.w;
        #pragma unroll
        for (int o = 16; o; o >>= 1) ss += __shfl_xor_sync(0xffffffffu, ss, o);
        if ((tid & 31) == 0) red[tid >> 5] = ss;
        __syncthreads();
        if (tid < 8) {
            float s2 = red[tid];
            #pragma unroll
            for (int o = 4; o; o >>= 1) s2 += __shfl_xor_sync(0xffu, s2, o);
            if (tid == 0) red[0] = s2;
        }
        __syncthreads();
        float rms = rsqrtf(red[0] * (1.0f / HH) + EPSF);
        float4 tv;
        tv.x = v.x * rms * sc.x; tv.y = v.y * rms * sc.y;
        tv.z = v.z * rms * sc.z; tv.w = v.w * rms * sc.w;
        *((float4*)ts + tid) = tv;
        uint4 u;
        u.x = f2tf(tv.x); u.y = f2tf(tv.y); u.z = f2tf(tv.z); u.w = f2tf(tv.w);
        *((uint4*)(g_t + (size_t)t * HH) + tid) = u;
        __syncthreads();

        int g = tid >> 4;
        int j = tid & 15;
        const float* wr = gw + g * HH;
        float sum = 0.f;
        #pragma unroll 8
        for (int h = j; h < HH; h += 16) sum += ts[h] * wr[h];
        #pragma unroll
        for (int o = 8; o; o >>= 1) sum += __shfl_xor_sync(0xffffffffu, sum, o);
        if (j == 0) gv[g] = sum + gate_b[g];
        __syncthreads();

        if (tid == 0) {
            float vals[KTOP];
            int   idx[KTOP];
            bool  used[NE];
            #pragma unroll
            for (int e = 0; e < NE; e++) used[e] = false;
            #pragma unroll
            for (int k = 0; k < KTOP; k++) {
                float best = -INFINITY; int bi = 0;
                for (int e = 0; e < NE; e++)
                    if (!used[e] && gv[e] > best) { best = gv[e]; bi = e; }
                used[bi] = true; vals[k] = best; idx[k] = bi;
            }
            float m = vals[0];
            float se = 0.f, w[KTOP];
            #pragma unroll
            for (int k = 0; k < KTOP; k++) { w[k] = __expf(vals[k] - m); se += w[k]; }
            float inv = 1.0f / se;
            #pragma unroll
            for (int k = 0; k < KTOP; k++) {
                int slot = t * KTOP + k;
                g_slot_w[slot] = w[k] * inv;
                int pos = atomicAdd(&g_expert_cnt[idx[k]], 1);
                g_expert_slots[idx[k] * TT + pos] = slot;
            }
        }
        __syncthreads();
    }
}

// ================= tf32 GEMMs: BK=32, pure cp.async, 3-stage ===================
// 128x128 block, 4 warps (2x2, 64x64 tiles), ldmatrix frags.
// Both operands cp.async from pre-rounded tf32 sources. 32 iterations
// (half the sync/wait overhead of BK=16); 4 independent ks-sections per iter.
// 2 CTAs/SM (216 KB smem).

#define GEMM32_BODY(EPILOGUE)                                                       \
    int lane = tid & 31, wid = tid >> 5;                                            \
    int wm = wid & 1, wn = wid >> 1;                                                \
    int grp = lane >> 2, tig = lane & 3;                                            \
    int rA = (lane & 7) + (((lane >> 3) & 1) << 3);                                 \
    int kA = (lane >> 4) << 2;                                                      \
    int rB = (lane & 7) + ((lane >> 4) << 3);                                       \
    int kB = ((lane >> 3) & 1) << 2;                                                \
    unsigned aAddr = (unsigned)__cvta_generic_to_shared(&As[(wm * 64 + rA) * PAD + kA]); \
    unsigned bAddr = (unsigned)__cvta_generic_to_shared(&Bs[(wn * 64 + rB) * PAD + kB]); \
    float acc[4][8][4] = {};                                                        \
    /* prologue: stages 0,1 via cp.async (16 cp16/thread each) */                   \
    _Pragma("unroll")                                                               \
    for (int c = 0; c < 2; c++) {                                                   \
        _Pragma("unroll")                                                           \
        for (int i = 0; i < 4; i++) {                                               \
            cp16(aDst[i] + c * STGB, aptr[i] + c * BK);                             \
            cp16(aDst[i] + c * STGB + 16, aptr[i] + c * BK + 4);                    \
            cp16(bDst[i] + c * STGB, bptr[i] + c * BK);                             \
            cp16(bDst[i] + c * STGB + 16, bptr[i] + c * BK + 4);                    \
        }                                                                           \
        CP_COMMIT();                                                                \
    }                                                                               \
    const int NKT = 1024 / BK;   /* 32 */                                           \
    for (int kb = 0; kb < NKT; kb++) {                                              \
        int cur = kb % NSTG;                                                        \
        CP_WAIT1();                                                                 \
        __syncthreads();                                                            \
        if (kb + 2 < NKT) {                                                         \
            int st = (kb + 2) % NSTG;                                               \
            int ko = (kb + 2) * BK;                                                 \
            _Pragma("unroll")                                                       \
            for (int i = 0; i < 4; i++) {                                           \
                cp16(aDst[i] + st * STGB, aptr[i] + ko);                            \
                cp16(aDst[i] + st * STGB + 16, aptr[i] + ko + 4);                   \
                cp16(bDst[i] + st * STGB, bptr[i] + ko);                            \
                cp16(bDst[i] + st * STGB + 16, bptr[i] + ko + 4);                   \
            }                                                                       \
        }                                                                           \
        CP_COMMIT();                                                                \
        unsigned aOff = aAddr + (unsigned)(cur * STGB);                             \
        unsigned bOff = bAddr + (unsigned)(cur * STGB);                             \
        _Pragma("unroll")                                                           \
        for (int ks = 0; ks < 4; ks++) {                                            \
            unsigned afr[4][4], bfr[4][4];                                          \
            _Pragma("unroll")                                                       \
            for (int sm2 = 0; sm2 < 4; sm2++)                                       \
                ldsm4(afr[sm2], aOff + (unsigned)((sm2 * 16 * PAD + ks * 8) * 4));  \
            _Pragma("unroll")                                                       \
            for (int p = 0; p < 4; p++)                                             \
                ldsm4(bfr[p], bOff + (unsigned)((p * 16 * PAD + ks * 8) * 4));      \
            _Pragma("unroll")                                                       \
            for (int sm2 = 0; sm2 < 4; sm2++)                                       \
                _Pragma("unroll")                                                   \
                for (int sn = 0; sn < 8; sn++)                                      \
                    mma_tf32(acc[sm2][sn], afr[sm2], &bfr[sn >> 1][(sn & 1) * 2]);  \
        }                                                                           \
    }                                                                               \
    EPILOGUE

// ---------------- mlp1: GEMM1 (pre-gathered even w1 rows) + bias + swiglu -----
__global__ void __launch_bounds__(128, 2) mlp1_kernel(const float* __restrict__ b1) {
    int e = blockIdx.z;
    int cnt = g_expert_cnt[e];
    int mt = blockIdx.y;
    if (mt * BM >= cnt) return;
    int ntB = blockIdx.x * BN;

    extern __shared__ __align__(16) unsigned smem[];
    unsigned* As = smem;
    unsigned* Bs = smem + NSTG * STG_WORDS;
    __shared__ int slots[BM];

    int tid = threadIdx.x;
    {
        int idx = mt * BM + tid;
        slots[tid] = (idx < cnt) ? g_expert_slots[e * TT + idx] : -1;
    }
    __syncthreads();

    int sr = tid >> 2;                 // 0..31
    int kq = (tid & 3) * 8;            // 0,8,16,24
    const float* w1e = g_w1r + (size_t)e * II * HH;
    const float* aptr[4];
    const float* bptr[4];
    unsigned aDst[4], bDst[4];
    #pragma unroll
    for (int i = 0; i < 4; i++) {
        int row = sr + i * 32;
        int s = slots[row];
        aptr[i] = g_t + (size_t)((s >= 0) ? (s >> 2) : 0) * HH + kq;
        bptr[i] = w1e + (size_t)(ntB + row) * HH + kq;
        aDst[i] = (unsigned)__cvta_generic_to_shared(&As[row * PAD + kq]);
        bDst[i] = (unsigned)__cvta_generic_to_shared(&Bs[row * PAD + kq]);
    }

    GEMM32_BODY(
        const float* b1e = b1 + e * (2 * II);
        _Pragma("unroll")
        for (int sm2 = 0; sm2 < 4; sm2++) {
            int rbase = wm * 64 + sm2 * 16 + grp;
            _Pragma("unroll")
            for (int half = 0; half < 2; half++) {
                int row = rbase + half * 8;
                int slot = slots[row];
                if (slot < 0) continue;
                float* srow = g_s + (size_t)slot * II;
                _Pragma("unroll")
                for (int sn = 0; sn < 8; sn++) {
                    int n = ntB + wn * 64 + sn * 8 + 2 * tig;
                    _Pragma("unroll")
                    for (int cc = 0; cc < 2; cc++) {
                        float hsum = acc[sm2][sn][half * 2 + cc] + b1e[2 * (n + cc)];
                        float gl = fminf(hsum, LIMITF);
                        float sig = 1.0f / (1.0f + __expf(-ALPHAF * gl));
                        srow[n + cc] = __uint_as_float(f2tf(gl * sig * (LIMITF + 1.0f)));
                    }
                }
            }
        }
    )
}

// ---------------- mlp2: GEMM2 + bias, scaled by routing weight ----------------
__global__ void __launch_bounds__(128, 2) mlp2_kernel(const float* __restrict__ b2) {
    int e = blockIdx.z;
    int cnt = g_expert_cnt[e];
    int mt = blockIdx.y;
    if (mt * BM >= cnt) return;
    int ntB = blockIdx.x * BN;

    extern __shared__ __align__(16) unsigned smem[];
    unsigned* As = smem;
    unsigned* Bs = smem + NSTG * STG_WORDS;
    __shared__ int slots[BM];

    int tid = threadIdx.x;
    {
        int idx = mt * BM + tid;
        slots[tid] = (idx < cnt) ? g_expert_slots[e * TT + idx] : -1;
    }
    __syncthreads();

    int sr = tid >> 2;
    int kq = (tid & 3) * 8;
    const float* w2e = g_w2r + (size_t)e * HH * II;
    const float* aptr[4];
    const float* bptr[4];
    unsigned aDst[4], bDst[4];
    #pragma unroll
    for (int i = 0; i < 4; i++) {
        int row = sr + i * 32;
        int s = slots[row];
        aptr[i] = g_s + (size_t)((s >= 0) ? s : 0) * II + kq;
        bptr[i] = w2e + (size_t)(ntB + row) * II + kq;
        aDst[i] = (unsigned)__cvta_generic_to_shared(&As[row * PAD + kq]);
        bDst[i] = (unsigned)__cvta_generic_to_shared(&Bs[row * PAD + kq]);
    }

    GEMM32_BODY(
        const float* b2e = b2 + e * HH;
        _Pragma("unroll")
        for (int sm2 = 0; sm2 < 4; sm2++) {
            int rbase = wm * 64 + sm2 * 16 + grp;
            _Pragma("unroll")
            for (int half = 0; half < 2; half++) {
                int row = rbase + half * 8;
                int slot = slots[row];
                if (slot < 0) continue;
                float rw = g_slot_w[slot];
                float* yrow = g_y + (size_t)slot * HH;
                _Pragma("unroll")
                for (int sn = 0; sn < 8; sn++) {
                    int n = ntB + wn * 64 + sn * 8 + 2 * tig;
                    _Pragma("unroll")
                    for (int cc = 0; cc < 2; cc++)
                        yrow[n + cc] = (acc[sm2][sn][half * 2 + cc] + b2e[n + cc]) * rw;
                }
            }
        }
    )
}

// ---------------- finalize: out = x + sum_k y[t*4+k] --------------------------
__global__ void finalize_kernel(const float* __restrict__ x,
                                float* __restrict__ out) {
    int qi = blockIdx.x * 256 + threadIdx.x;
    int t = qi >> 8;
    int h4 = qi & 255;
    float4 v = *((const float4*)x + qi);
    const float4* yb = (const float4*)(g_y + (size_t)t * KTOP * HH) + h4;
    float4 a = yb[0], b = yb[256], c = yb[512], d = yb[768];
    v.x += a.x + b.x + c.x + d.x;
    v.y += a.y + b.y + c.y + d.y;
    v.z += a.z + b.z + c.z + d.z;
    v.w += a.w + b.w + c.w + d.w;
    *((float4*)out + qi) = v;
}

// ---------------- launcher -----------------------------------------------------
extern "C" void kernel_launch(void* const* d_in, const int* in_sizes, int n_in,
                              void* d_out, int out_size) {
    const float* x      = (const float*)d_in[0];
    const float* scale  = (const float*)d_in[1];
    const float* gate_w = (const float*)d_in[2];
    const float* gate_b = (const float*)d_in[3];
    const float* w1     = (const float*)d_in[4];
    const float* b1     = (const float*)d_in[5];
    const float* w2     = (const float*)d_in[6];
    const float* b2     = (const float*)d_in[7];
    float* out = (float*)d_out;

    cudaFuncSetAttribute(norm_gate_kernel, cudaFuncAttributeMaxDynamicSharedMemorySize, NG_SMEM);
    cudaFuncSetAttribute(mlp1_kernel, cudaFuncAttributeMaxDynamicSharedMemorySize, SMEM_BYTES);
    cudaFuncSetAttribute(mlp2_kernel, cudaFuncAttributeMaxDynamicSharedMemorySize, SMEM_BYTES);

    zero_cnt_kernel<<<1, 32>>>();
    prep_w1_kernel<<<(NE * II * HH / 4) / 256, 256>>>(w1);
    prep_w2_kernel<<<(NE * HH * II / 4) / 256, 256>>>(w2);
    norm_gate_kernel<<<TT / TOK_PER_BLK, 256, NG_SMEM>>>(x, scale, gate_w, gate_b);

    dim3 g1(II / BN, TT / BM, NE);    // (8, 16, 16)
    mlp1_kernel<<<g1, 128, SMEM_BYTES>>>(b1);

    dim3 g2(HH / BN, TT / BM, NE);
    mlp2_kernel<<<g2, 128, SMEM_BYTES>>>(b2);

    finalize_kernel<<<(TT * HH) / 1024, 256>>>(x, out);
}

// round 17
// speedup vs baseline: 1.2906x; 1.2906x over previous
#include <cuda_runtime.h>
#include <math.h>

#define TT 2048
#define HH 1024
#define II 1024
#define NE 16
#define KTOP 4
#define EPSF 1e-5f
#define ALPHAF 1.702f
#define LIMITF 7.0f

#define BM 128
#define BN 128
#define BK 16
#define PAD 20
#define NSTG 3
#define STG_WORDS (128 * PAD)
#define SMEM_BYTES (NSTG * STG_WORDS * 4 * 2)      // 61440

// ---------------- scratch (static device globals; no allocation) -------------
__device__ __align__(16) float g_t[TT * HH];            // tf32-rounded rmsnorm out
__device__ __align__(16) float g_s[TT * KTOP * II];     // tf32-rounded swiglu out
__device__ __align__(16) float g_y[TT * KTOP * HH];
__device__ float g_slot_w[TT * KTOP];
__device__ int   g_expert_cnt[NE];
__device__ int   g_expert_slots[NE * TT];

// ---------------- helpers ------------------------------------------------------
__device__ __forceinline__ unsigned f2tf(float f) {
    unsigned r;
    asm("cvt.rna.tf32.f32 %0, %1;" : "=r"(r) : "f"(f));
    return r;
}

__device__ __forceinline__ void mma_tf32(float* d, const unsigned* a, const unsigned* b) {
    asm volatile(
        "mma.sync.aligned.m16n8k8.row.col.f32.tf32.tf32.f32 "
        "{%0,%1,%2,%3}, {%4,%5,%6,%7}, {%8,%9}, {%0,%1,%2,%3};"
        : "+f"(d[0]), "+f"(d[1]), "+f"(d[2]), "+f"(d[3])
        : "r"(a[0]), "r"(a[1]), "r"(a[2]), "r"(a[3]), "r"(b[0]), "r"(b[1]));
}

__device__ __forceinline__ void ldsm4(unsigned* r, unsigned addr) {
    asm volatile("ldmatrix.sync.aligned.m8n8.x4.shared.b16 {%0,%1,%2,%3}, [%4];"
        : "=r"(r[0]), "=r"(r[1]), "=r"(r[2]), "=r"(r[3]) : "r"(addr));
}

__device__ __forceinline__ void cp16(unsigned dst, const void* src) {
    asm volatile("cp.async.cg.shared.global [%0], [%1], 16;" :: "r"(dst), "l"(src));
}
#define CP_COMMIT() asm volatile("cp.async.commit_group;")
#define CP_WAIT1()  asm volatile("cp.async.wait_group 1;")

// ---------------- kernel 0 -----------------------------------------------------
__global__ void zero_cnt_kernel() {
    if (threadIdx.x < NE) g_expert_cnt[threadIdx.x] = 0;
}

// ---------------- kernel 1: fused RMSNorm + gate + top4 + routing -------------
// 1 token per block (measured-fastest variant: 21.7 us). Gate logits from
// UNROUNDED t; g_t written tf32-RNA for cp.async staging in mlp1.
__global__ void norm_gate_kernel(const float* __restrict__ x,
                                 const float* __restrict__ scale,
                                 const float* __restrict__ gate_w,
                                 const float* __restrict__ gate_b) {
    int t = blockIdx.x;
    int tid = threadIdx.x;
    __shared__ float ts[HH];
    __shared__ float gv[NE];
    __shared__ float red[8];

    float4 v = *((const float4*)(x + (size_t)t * HH) + tid);
    float ss = v.x * v.x + v.y * v.y + v.z * v.z + v.w * v.w;
    #pragma unroll
    for (int o = 16; o; o >>= 1) ss += __shfl_xor_sync(0xffffffffu, ss, o);
    if ((tid & 31) == 0) red[tid >> 5] = ss;
    __syncthreads();
    if (tid < 8) {
        float s2 = red[tid];
        #pragma unroll
        for (int o = 4; o; o >>= 1) s2 += __shfl_xor_sync(0xffu, s2, o);
        if (tid == 0) red[0] = s2;
    }
    __syncthreads();
    float rms = rsqrtf(red[0] * (1.0f / HH) + EPSF);
    float4 sc = *((const float4*)scale + tid);
    float4 tv;
    tv.x = v.x * rms * sc.x; tv.y = v.y * rms * sc.y;
    tv.z = v.z * rms * sc.z; tv.w = v.w * rms * sc.w;
    *((float4*)ts + tid) = tv;
    uint4 u;
    u.x = f2tf(tv.x); u.y = f2tf(tv.y); u.z = f2tf(tv.z); u.w = f2tf(tv.w);
    *((uint4*)(g_t + (size_t)t * HH) + tid) = u;
    __syncthreads();

    int g = tid >> 4;
    int j = tid & 15;
    const float* wr = gate_w + g * HH;
    float sum = 0.f;
    for (int h = j; h < HH; h += 16) sum += ts[h] * wr[h];
    #pragma unroll
    for (int o = 8; o; o >>= 1) sum += __shfl_xor_sync(0xffffffffu, sum, o);
    if (j == 0) gv[g] = sum + gate_b[g];
    __syncthreads();

    if (tid == 0) {
        float vals[KTOP];
        int   idx[KTOP];
        bool  used[NE];
        #pragma unroll
        for (int e = 0; e < NE; e++) used[e] = false;
        #pragma unroll
        for (int k = 0; k < KTOP; k++) {
            float best = -INFINITY; int bi = 0;
            for (int e = 0; e < NE; e++)
                if (!used[e] && gv[e] > best) { best = gv[e]; bi = e; }
            used[bi] = true; vals[k] = best; idx[k] = bi;
        }
        float m = vals[0];
        float se = 0.f, w[KTOP];
        #pragma unroll
        for (int k = 0; k < KTOP; k++) { w[k] = __expf(vals[k] - m); se += w[k]; }
        float inv = 1.0f / se;
        #pragma unroll
        for (int k = 0; k < KTOP; k++) {
            int slot = t * KTOP + k;
            g_slot_w[slot] = w[k] * inv;
            int pos = atomicAdd(&g_expert_cnt[idx[k]], 1);
            g_expert_slots[idx[k] * TT + pos] = slot;
        }
    }
}

// ================= tf32 GEMMs (R14 core: R8 + hoisted STS/LDG) =================
// 128x128 block, 4 warps (2x2, 64x64 tiles), ldmatrix frags, 3-stage pipeline.
// A via cp.async (pre-rounded tf32); B via LDG->cvt.rna->STS one tile ahead.
// STS(kb+1) and LDG(kb+2) hoisted ABOVE the wait+sync (stage-disjoint mod 3).

// ---------------- mlp1: GEMM1 (even w1 rows) + bias + swiglu ------------------
__global__ void __launch_bounds__(128, 2) mlp1_kernel(const float* __restrict__ w1,
                                                      const float* __restrict__ b1) {
    int e = blockIdx.z;
    int cnt = g_expert_cnt[e];
    int mt = blockIdx.y;
    if (mt * BM >= cnt) return;
    int ntB = blockIdx.x * BN;

    extern __shared__ __align__(16) unsigned smem[];
    unsigned* As = smem;
    unsigned* Bs = smem + NSTG * STG_WORDS;
    __shared__ int slots[BM];

    int tid = threadIdx.x;
    {
        int idx = mt * BM + tid;
        slots[tid] = (idx < cnt) ? g_expert_slots[e * TT + idx] : -1;
    }
    __syncthreads();

    int lane = tid & 31, wid = tid >> 5;
    int wm = wid & 1, wn = wid >> 1;
    int grp = lane >> 2, tig = lane & 3;
    int rA = (lane & 7) + (((lane >> 3) & 1) << 3);
    int kA = (lane >> 4) << 2;
    int rB = (lane & 7) + ((lane >> 4) << 3);
    int kB = ((lane >> 3) & 1) << 2;
    unsigned aAddr = (unsigned)__cvta_generic_to_shared(&As[(wm * 64 + rA) * PAD + kA]);
    unsigned bAddr = (unsigned)__cvta_generic_to_shared(&Bs[(wn * 64 + rB) * PAD + kB]);

    int sr = tid >> 2;
    int kq = (tid & 3) * 4;
    const float* w1e = w1 + (size_t)e * (2 * II) * HH;
    const float* aptr[4];
    const float* bptr[4];
    unsigned aDst[4];
    #pragma unroll
    for (int i = 0; i < 4; i++) {
        int row = sr + i * 32;
        int s = slots[row];
        aptr[i] = g_t + (size_t)((s >= 0) ? (s >> 2) : 0) * HH + kq;
        bptr[i] = w1e + (size_t)(2 * (ntB + row)) * HH + kq;
        aDst[i] = (unsigned)__cvta_generic_to_shared(&As[row * PAD + kq]);
    }

    float acc[4][8][4] = {};
    float4 bv[4];

    // prologue: B stage0 LDG+cvt+STS; A stage0/1 cp.async; B stage1 LDG
    #pragma unroll
    for (int i = 0; i < 4; i++) {
        float4 b0 = *(const float4*)(bptr[i]);
        uint4 u;
        u.x = f2tf(b0.x); u.y = f2tf(b0.y); u.z = f2tf(b0.z); u.w = f2tf(b0.w);
        *(uint4*)&Bs[(sr + i * 32) * PAD + kq] = u;
    }
    #pragma unroll
    for (int i = 0; i < 4; i++) cp16(aDst[i], aptr[i]);
    CP_COMMIT();
    #pragma unroll
    for (int i = 0; i < 4; i++) cp16(aDst[i] + STG_WORDS * 4, aptr[i] + BK);
    CP_COMMIT();
    #pragma unroll
    for (int i = 0; i < 4; i++) bv[i] = *(const float4*)(bptr[i] + BK);

    const int NKT = HH / BK;
    for (int kb = 0; kb < NKT; kb++) {
        int cur = kb % NSTG;
        if (kb + 1 < NKT) {                      // STS B stage kb+1 (pre-sync; disjoint)
            int st = (kb + 1) % NSTG;
            #pragma unroll
            for (int i = 0; i < 4; i++) {
                uint4 u;
                u.x = f2tf(bv[i].x); u.y = f2tf(bv[i].y);
                u.z = f2tf(bv[i].z); u.w = f2tf(bv[i].w);
                *(uint4*)&Bs[st * STG_WORDS + (sr + i * 32) * PAD + kq] = u;
            }
        }
        if (kb + 2 < NKT) {                      // B LDG stage kb+2 (early issue)
            int ko = (kb + 2) * BK;
            #pragma unroll
            for (int i = 0; i < 4; i++) bv[i] = *(const float4*)(bptr[i] + ko);
        }
        CP_WAIT1();
        __syncthreads();
        if (kb + 2 < NKT) {                      // A cp.async stage kb+2
            int st = (kb + 2) % NSTG;
            int ko = (kb + 2) * BK;
            #pragma unroll
            for (int i = 0; i < 4; i++)
                cp16(aDst[i] + (unsigned)(st * STG_WORDS * 4), aptr[i] + ko);
        }
        CP_COMMIT();
        unsigned aOff = aAddr + (unsigned)(cur * STG_WORDS * 4);
        unsigned bOff = bAddr + (unsigned)(cur * STG_WORDS * 4);
        #pragma unroll
        for (int ks = 0; ks < 2; ks++) {
            unsigned afr[4][4], bfr[4][4];
            #pragma unroll
            for (int sm = 0; sm < 4; sm++)
                ldsm4(afr[sm], aOff + (unsigned)((sm * 16 * PAD + ks * 8) * 4));
            #pragma unroll
            for (int p = 0; p < 4; p++)
                ldsm4(bfr[p], bOff + (unsigned)((p * 16 * PAD + ks * 8) * 4));
            #pragma unroll
            for (int sm = 0; sm < 4; sm++)
                #pragma unroll
                for (int sn = 0; sn < 8; sn++)
                    mma_tf32(acc[sm][sn], afr[sm], &bfr[sn >> 1][(sn & 1) * 2]);
        }
    }

    const float* b1e = b1 + e * (2 * II);
    #pragma unroll
    for (int sm = 0; sm < 4; sm++) {
        int rbase = wm * 64 + sm * 16 + grp;
        #pragma unroll
        for (int half = 0; half < 2; half++) {
            int row = rbase + half * 8;
            int slot = slots[row];
            if (slot < 0) continue;
            float* srow = g_s + (size_t)slot * II;
            #pragma unroll
            for (int sn = 0; sn < 8; sn++) {
                int n = ntB + wn * 64 + sn * 8 + 2 * tig;
                #pragma unroll
                for (int cc = 0; cc < 2; cc++) {
                    float hsum = acc[sm][sn][half * 2 + cc] + b1e[2 * (n + cc)];
                    float gl = fminf(hsum, LIMITF);
                    float sig = 1.0f / (1.0f + __expf(-ALPHAF * gl));
                    srow[n + cc] = __uint_as_float(f2tf(gl * sig * (LIMITF + 1.0f)));
                }
            }
        }
    }
}

// ---------------- mlp2: GEMM2 + bias, scaled by routing weight ----------------
__global__ void __launch_bounds__(128, 2) mlp2_kernel(const float* __restrict__ w2,
                                                      const float* __restrict__ b2) {
    int e = blockIdx.z;
    int cnt = g_expert_cnt[e];
    int mt = blockIdx.y;
    if (mt * BM >= cnt) return;
    int ntB = blockIdx.x * BN;

    extern __shared__ __align__(16) unsigned smem[];
    unsigned* As = smem;
    unsigned* Bs = smem + NSTG * STG_WORDS;
    __shared__ int slots[BM];

    int tid = threadIdx.x;
    {
        int idx = mt * BM + tid;
        slots[tid] = (idx < cnt) ? g_expert_slots[e * TT + idx] : -1;
    }
    __syncthreads();

    int lane = tid & 31, wid = tid >> 5;
    int wm = wid & 1, wn = wid >> 1;
    int grp = lane >> 2, tig = lane & 3;
    int rA = (lane & 7) + (((lane >> 3) & 1) << 3);
    int kA = (lane >> 4) << 2;
    int rB = (lane & 7) + ((lane >> 4) << 3);
    int kB = ((lane >> 3) & 1) << 2;
    unsigned aAddr = (unsigned)__cvta_generic_to_shared(&As[(wm * 64 + rA) * PAD + kA]);
    unsigned bAddr = (unsigned)__cvta_generic_to_shared(&Bs[(wn * 64 + rB) * PAD + kB]);

    int sr = tid >> 2;
    int kq = (tid & 3) * 4;
    const float* w2e = w2 + (size_t)e * HH * II;
    const float* aptr[4];
    const float* bptr[4];
    unsigned aDst[4];
    #pragma unroll
    for (int i = 0; i < 4; i++) {
        int row = sr + i * 32;
        int s = slots[row];
        aptr[i] = g_s + (size_t)((s >= 0) ? s : 0) * II + kq;
        bptr[i] = w2e + (size_t)(ntB + row) * II + kq;
        aDst[i] = (unsigned)__cvta_generic_to_shared(&As[row * PAD + kq]);
    }

    float acc[4][8][4] = {};
    float4 bv[4];

    #pragma unroll
    for (int i = 0; i < 4; i++) {
        float4 b0 = *(const float4*)(bptr[i]);
        uint4 u;
        u.x = f2tf(b0.x); u.y = f2tf(b0.y); u.z = f2tf(b0.z); u.w = f2tf(b0.w);
        *(uint4*)&Bs[(sr + i * 32) * PAD + kq] = u;
    }
    #pragma unroll
    for (int i = 0; i < 4; i++) cp16(aDst[i], aptr[i]);
    CP_COMMIT();
    #pragma unroll
    for (int i = 0; i < 4; i++) cp16(aDst[i] + STG_WORDS * 4, aptr[i] + BK);
    CP_COMMIT();
    #pragma unroll
    for (int i = 0; i < 4; i++) bv[i] = *(const float4*)(bptr[i] + BK);

    const int NKT = II / BK;
    for (int kb = 0; kb < NKT; kb++) {
        int cur = kb % NSTG;
        if (kb + 1 < NKT) {
            int st = (kb + 1) % NSTG;
            #pragma unroll
            for (int i = 0; i < 4; i++) {
                uint4 u;
                u.x = f2tf(bv[i].x); u.y = f2tf(bv[i].y);
                u.z = f2tf(bv[i].z); u.w = f2tf(bv[i].w);
                *(uint4*)&Bs[st * STG_WORDS + (sr + i * 32) * PAD + kq] = u;
            }
        }
        if (kb + 2 < NKT) {
            int ko = (kb + 2) * BK;
            #pragma unroll
            for (int i = 0; i < 4; i++) bv[i] = *(const float4*)(bptr[i] + ko);
        }
        CP_WAIT1();
        __syncthreads();
        if (kb + 2 < NKT) {
            int st = (kb + 2) % NSTG;
            int ko = (kb + 2) * BK;
            #pragma unroll
            for (int i = 0; i < 4; i++)
                cp16(aDst[i] + (unsigned)(st * STG_WORDS * 4), aptr[i] + ko);
        }
        CP_COMMIT();
        unsigned aOff = aAddr + (unsigned)(cur * STG_WORDS * 4);
        unsigned bOff = bAddr + (unsigned)(cur * STG_WORDS * 4);
        #pragma unroll
        for (int ks = 0; ks < 2; ks++) {
            unsigned afr[4][4], bfr[4][4];
            #pragma unroll
            for (int sm = 0; sm < 4; sm++)
                ldsm4(afr[sm], aOff + (unsigned)((sm * 16 * PAD + ks * 8) * 4));
            #pragma unroll
            for (int p = 0; p < 4; p++)
                ldsm4(bfr[p], bOff + (unsigned)((p * 16 * PAD + ks * 8) * 4));
            #pragma unroll
            for (int sm = 0; sm < 4; sm++)
                #pragma unroll
                for (int sn = 0; sn < 8; sn++)
                    mma_tf32(acc[sm][sn], afr[sm], &bfr[sn >> 1][(sn & 1) * 2]);
        }
    }

    const float* b2e = b2 + e * HH;
    #pragma unroll
    for (int sm = 0; sm < 4; sm++) {
        int rbase = wm * 64 + sm * 16 + grp;
        #pragma unroll
        for (int half = 0; half < 2; half++) {
            int row = rbase + half * 8;
            int slot = slots[row];
            if (slot < 0) continue;
            float rw = g_slot_w[slot];
            float* yrow = g_y + (size_t)slot * HH;
            #pragma unroll
            for (int sn = 0; sn < 8; sn++) {
                int n = ntB + wn * 64 + sn * 8 + 2 * tig;
                #pragma unroll
                for (int cc = 0; cc < 2; cc++)
                    yrow[n + cc] = (acc[sm][sn][half * 2 + cc] + b2e[n + cc]) * rw;
            }
        }
    }
}

// ---------------- finalize: out = x + sum_k y[t*4+k] --------------------------
__global__ void finalize_kernel(const float* __restrict__ x,
                                float* __restrict__ out) {
    int qi = blockIdx.x * 256 + threadIdx.x;
    int t = qi >> 8;
    int h4 = qi & 255;
    float4 v = *((const float4*)x + qi);
    const float4* yb = (const float4*)(g_y + (size_t)t * KTOP * HH) + h4;
    float4 a = yb[0], b = yb[256], c = yb[512], d = yb[768];
    v.x += a.x + b.x + c.x + d.x;
    v.y += a.y + b.y + c.y + d.y;
    v.z += a.z + b.z + c.z + d.z;
    v.w += a.w + b.w + c.w + d.w;
    *((float4*)out + qi) = v;
}

// ---------------- launcher -----------------------------------------------------
extern "C" void kernel_launch(void* const* d_in, const int* in_sizes, int n_in,
                              void* d_out, int out_size) {
    const float* x      = (const float*)d_in[0];
    const float* scale  = (const float*)d_in[1];
    const float* gate_w = (const float*)d_in[2];
    const float* gate_b = (const float*)d_in[3];
    const float* w1     = (const float*)d_in[4];
    const float* b1     = (const float*)d_in[5];
    const float* w2     = (const float*)d_in[6];
    const float* b2     = (const float*)d_in[7];
    float* out = (float*)d_out;

    cudaFuncSetAttribute(mlp1_kernel, cudaFuncAttributeMaxDynamicSharedMemorySize, SMEM_BYTES);
    cudaFuncSetAttribute(mlp2_kernel, cudaFuncAttributeMaxDynamicSharedMemorySize, SMEM_BYTES);

    zero_cnt_kernel<<<1, 32>>>();
    norm_gate_kernel<<<TT, 256>>>(x, scale, gate_w, gate_b);

    dim3 g1(II / BN, TT / BM, NE);    // (8, 16, 16)
    mlp1_kernel<<<g1, 128, SMEM_BYTES>>>(w1, b1);

    dim3 g2(HH / BN, TT / BM, NE);
    mlp2_kernel<<<g2, 128, SMEM_BYTES>>>(w2, b2);

    finalize_kernel<<<(TT * HH) / 1024, 256>>>(x, out);
}